// round 2
// baseline (speedup 1.0000x reference)
#include <cuda_runtime.h>
#include <math.h>

// Problem shapes (fixed by the dataset)
#define Bb 4
#define Tt 16
#define Ss 256
#define Dd 512
#define Nn 8
#define Mm (Bb * Ss)   // 1024 GEMM rows
#define Kk Dd          // 512  GEMM K
#define Nc (Dd * Nn)   // 4096 GEMM cols

// Scratch: sigmoid(emb @ W + b), layout [B*S, D*N] == [B,S,D,N] row-major. 16.7 MB.
__device__ __align__(16) float g_pop_rates[(size_t)Mm * Nc];

// ---------------------------------------------------------------------------
// Kernel 1: fp32 GEMM + bias + sigmoid -> g_pop_rates
// 128x128 tile, BK=16, 256 threads, 8x8 microtile, f32x2 packed FMA.
// ---------------------------------------------------------------------------
__device__ __forceinline__ void ffma2(unsigned long long& d,
                                      unsigned long long a,
                                      unsigned long long b) {
    asm("fma.rn.f32x2 %0, %1, %2, %0;" : "+l"(d) : "l"(a), "l"(b));
}

__global__ __launch_bounds__(256) void gemm_sig_kernel(
    const float* __restrict__ E,     // [Mm, Kk]
    const float* __restrict__ W,     // [Kk, Nc]
    const float* __restrict__ bias)  // [Nc]
{
    __shared__ float As[16][132];   // transposed A tile, padded
    __shared__ float Bs[16][128];

    const int tid = threadIdx.x;
    const int bm = blockIdx.y * 128;
    const int bn = blockIdx.x * 128;
    const int tm = (tid >> 4) * 8;   // 0..120
    const int tn = (tid & 15) * 8;   // 0..120

    unsigned long long acc[8][4];
#pragma unroll
    for (int i = 0; i < 8; i++)
#pragma unroll
        for (int j = 0; j < 4; j++) acc[i][j] = 0ull;

    for (int k0 = 0; k0 < Kk; k0 += 16) {
        // Load A tile 128x16 (transpose into As[k][m])
#pragma unroll
        for (int r = 0; r < 2; r++) {
            int i = tid + 256 * r;          // 0..511 float4s
            int row = i >> 2;               // 0..127
            int kc = (i & 3) * 4;           // 0,4,8,12
            float4 v = *(const float4*)(E + (size_t)(bm + row) * Kk + k0 + kc);
            As[kc + 0][row] = v.x;
            As[kc + 1][row] = v.y;
            As[kc + 2][row] = v.z;
            As[kc + 3][row] = v.w;
        }
        // Load B tile 16x128
#pragma unroll
        for (int r = 0; r < 2; r++) {
            int i = tid + 256 * r;
            int row = i >> 5;               // 0..15
            int col = (i & 31) * 4;         // 0..124
            *(float4*)(&Bs[row][col]) =
                *(const float4*)(W + (size_t)(k0 + row) * Nc + bn + col);
        }
        __syncthreads();

#pragma unroll
        for (int kk = 0; kk < 16; kk++) {
            float4 a0 = *(const float4*)(&As[kk][tm]);
            float4 a1 = *(const float4*)(&As[kk][tm + 4]);
            unsigned long long b[4];
#pragma unroll
            for (int j = 0; j < 4; j++)
                b[j] = *(const unsigned long long*)(&Bs[kk][tn + 2 * j]);
            float a[8] = {a0.x, a0.y, a0.z, a0.w, a1.x, a1.y, a1.z, a1.w};
#pragma unroll
            for (int i = 0; i < 8; i++) {
                unsigned long long a2;
                asm("mov.b64 %0, {%1, %1};" : "=l"(a2) : "f"(a[i]));
#pragma unroll
                for (int j = 0; j < 4; j++) ffma2(acc[i][j], a2, b[j]);
            }
        }
        __syncthreads();
    }

    // Epilogue: bias + sigmoid -> g_pop_rates
#pragma unroll
    for (int i = 0; i < 8; i++) {
        int row = bm + tm + i;
#pragma unroll
        for (int j = 0; j < 4; j++) {
            int col = bn + tn + 2 * j;
            float lo, hi;
            asm("mov.b64 {%0, %1}, %2;" : "=f"(lo), "=f"(hi) : "l"(acc[i][j]));
            lo += bias[col];
            hi += bias[col + 1];
            float2 r;
            r.x = 1.0f / (1.0f + expf(-lo));
            r.y = 1.0f / (1.0f + expf(-hi));
            *(float2*)(g_pop_rates + (size_t)row * Nc + col) = r;
        }
    }
}

// ---------------------------------------------------------------------------
// Accurate fp32 sin (Cody-Waite 2-term pi reduction + degree-9 minimax).
// abs error ~1e-7 on |x| <= ~100; immune to --use_fast_math substitution.
// ---------------------------------------------------------------------------
__device__ __forceinline__ float my_sinf(float x) {
    const float INV_PI = 0.318309886183790672f;
    const float PI_HI = 3.14159274101257324f;      // float(pi)
    const float PI_LO = -8.74227765734758577e-08f; // pi - float(pi)
    float kf = rintf(x * INV_PI);
    float r = fmaf(-kf, PI_HI, x);
    r = fmaf(-kf, PI_LO, r);
    float s = r * r;
    float p = fmaf(s, 2.6083159809786593e-06f, -1.9810690719168633e-04f);
    p = fmaf(s, p, 8.3330785855650902e-03f);
    p = fmaf(s, p, -1.6666659712791443e-01f);
    float res = fmaf(r * s, p, r);
    int k = (int)kf;
    return (k & 1) ? -res : res;
}

// ---------------------------------------------------------------------------
// Kernel 2: fused encoder. One thread per (b,s,d), loop over T=16.
// Streams rate_rand + pop_rand + out; pop_rates held in registers across t.
// ---------------------------------------------------------------------------
__global__ __launch_bounds__(256) void encode_kernel(
    const float* __restrict__ emb,        // [B,S,D]
    const float* __restrict__ noise,      // [B,S,D]
    const float* __restrict__ freq_bands, // [D]
    const float* __restrict__ enc_w,      // [4]
    const float* __restrict__ rate_rand,  // [B,T,S,D]
    const float* __restrict__ pop_rand,   // [B,T,S,D,N]
    float* __restrict__ out)              // [B,T,S,D]
{
    const int idx = blockIdx.x * 256 + threadIdx.x;  // over B*S*D = 524288
    const int d = idx & (Dd - 1);
    const int s = (idx >> 9) & (Ss - 1);
    const int b = idx >> 17;

    // softmax over enc_weights (uniform inputs -> exact 0.25 each, but general)
    float w0 = enc_w[0], w1 = enc_w[1], w2 = enc_w[2], w3 = enc_w[3];
    {
        float mx = fmaxf(fmaxf(w0, w1), fmaxf(w2, w3));
        float e0 = expf(w0 - mx), e1 = expf(w1 - mx);
        float e2 = expf(w2 - mx), e3 = expf(w3 - mx);
        float inv = 1.0f / (e0 + e1 + e2 + e3);
        w0 = e0 * inv; w1 = e1 * inv; w2 = e2 * inv; w3 = e3 * inv;
    }

    const float e = emb[idx];
    const float nz = noise[idx];
    const float sig = 1.0f / (1.0f + expf(-e));
    float rate = sig * 0.9f + 0.05f + nz * 0.1f;
    rate = fminf(fmaxf(rate, 0.0f), 1.0f);
    const int st = (int)(sig * 15.0f);       // (T-1) = 15, trunc toward 0 (sig>0)
    const float phase = sig * 6.28318530717958647692f;
    const float freq = freq_bands[d];

    const float4* prp = (const float4*)(g_pop_rates + (size_t)idx * Nn);
    const float4 pr0 = prp[0];
    const float4 pr1 = prp[1];

    const float tstep = 6.28318530717958647692f / 15.0f;  // linspace(0,2pi,16) step

    const size_t base = (((size_t)b * Tt) * Ss + s) * Dd + d;
#pragma unroll 4
    for (int t = 0; t < Tt; t++) {
        const size_t o = base + (size_t)t * (Ss * Dd);
        const float rr = __ldg(rate_rand + o);
        const float4* pp = (const float4*)(pop_rand + o * Nn);
        const float4 q0 = __ldg(pp);
        const float4 q1 = __ldg(pp + 1);
        int cnt = (q0.x < pr0.x) + (q0.y < pr0.y) + (q0.z < pr0.z) + (q0.w < pr0.w)
                + (q1.x < pr1.x) + (q1.y < pr1.y) + (q1.z < pr1.z) + (q1.w < pr1.w);

        const float tval = (float)t * tstep;
        const float wave = my_sinf(freq * tval + phase);

        float val = w0 * ((rr < rate) ? 1.0f : 0.0f)
                  + w1 * ((t == st) ? 1.0f : 0.0f)
                  + w2 * ((float)cnt * 0.125f)
                  + w3 * ((wave > 0.5f) ? 1.0f : 0.0f);
        out[o] = val;
    }
}

// ---------------------------------------------------------------------------
// Launch
// ---------------------------------------------------------------------------
extern "C" void kernel_launch(void* const* d_in, const int* in_sizes, int n_in,
                              void* d_out, int out_size) {
    const float* emb       = (const float*)d_in[0]; // embeddings [B,S,D]
    const float* popW      = (const float*)d_in[1]; // pop_W [D, D*N]
    const float* popb      = (const float*)d_in[2]; // pop_b [D*N]
    const float* freq      = (const float*)d_in[3]; // freq_bands [D]
    const float* encw      = (const float*)d_in[4]; // enc_weights [4]
    const float* noise     = (const float*)d_in[5]; // rate_noise [B,S,D]
    const float* rate_rand = (const float*)d_in[6]; // [B,T,S,D]
    const float* pop_rand  = (const float*)d_in[7]; // [B,T,S,D,N]
    float* out = (float*)d_out;

    dim3 gg(Nc / 128, Mm / 128);   // 32 x 8
    gemm_sig_kernel<<<gg, 256>>>(emb, popW, popb);

    encode_kernel<<<(Mm * Dd) / 256, 256>>>(emb, noise, freq, encw,
                                            rate_rand, pop_rand, out);
}

// round 4
// speedup vs baseline: 1.5812x; 1.5812x over previous
#include <cuda_runtime.h>
#include <cuda_bf16.h>
#include <math.h>
#include <stdint.h>

// Problem shapes (fixed by the dataset)
#define Bb 4
#define Tt 16
#define Ss 256
#define Dd 512
#define Nn 8
#define Mm (Bb * Ss)   // 1024 GEMM rows
#define Kk Dd          // 512  GEMM K
#define Nc (Dd * Nn)   // 4096 GEMM cols

// ---------------------------------------------------------------------------
// Device scratch (no dynamic allocation allowed)
// ---------------------------------------------------------------------------
__device__ __align__(16) float         g_pop_rates[(size_t)Mm * Nc]; // 16.7 MB
__device__ __align__(16) __nv_bfloat16 g_Ehi[(size_t)Mm * Kk];       // [m][k]
__device__ __align__(16) __nv_bfloat16 g_Elo[(size_t)Mm * Kk];
__device__ __align__(16) __nv_bfloat16 g_Whi[(size_t)Kk * Nc];       // [k][n]
__device__ __align__(16) __nv_bfloat16 g_Wlo[(size_t)Kk * Nc];

// ---------------------------------------------------------------------------
// Fused bf16 hi/lo split conversion for E and W (elementwise, float4).
// ---------------------------------------------------------------------------
#define E_F4 ((Mm * Kk) / 4)      // 131072
#define W_F4 ((Kk * Nc) / 4)      // 524288

__device__ __forceinline__ void split4(float4 v, ushort4& hi, ushort4& lo) {
    __nv_bfloat16 h;
    h = __float2bfloat16(v.x); hi.x = __bfloat16_as_ushort(h);
    lo.x = __bfloat16_as_ushort(__float2bfloat16(v.x - __bfloat162float(h)));
    h = __float2bfloat16(v.y); hi.y = __bfloat16_as_ushort(h);
    lo.y = __bfloat16_as_ushort(__float2bfloat16(v.y - __bfloat162float(h)));
    h = __float2bfloat16(v.z); hi.z = __bfloat16_as_ushort(h);
    lo.z = __bfloat16_as_ushort(__float2bfloat16(v.z - __bfloat162float(h)));
    h = __float2bfloat16(v.w); hi.w = __bfloat16_as_ushort(h);
    lo.w = __bfloat16_as_ushort(__float2bfloat16(v.w - __bfloat162float(h)));
}

__global__ __launch_bounds__(256) void conv_kernel(const float* __restrict__ E,
                                                   const float* __restrict__ W) {
    int i = blockIdx.x * 256 + threadIdx.x;
    if (i < E_F4) {
        float4 v = ((const float4*)E)[i];
        ushort4 hi, lo;
        split4(v, hi, lo);
        ((ushort4*)g_Ehi)[i] = hi;
        ((ushort4*)g_Elo)[i] = lo;
    } else {
        int j = i - E_F4;
        if (j < W_F4) {
            float4 v = ((const float4*)W)[j];
            ushort4 hi, lo;
            split4(v, hi, lo);
            ((ushort4*)g_Whi)[j] = hi;
            ((ushort4*)g_Wlo)[j] = lo;
        }
    }
}

// ---------------------------------------------------------------------------
// mma.sync bf16 GEMM with 3-term split + bias + sigmoid epilogue.
// CTA tile 128x128, BK=32, 8 warps (warp tile 32x64), double-buffered cp.async.
// ---------------------------------------------------------------------------
#define BM 128
#define BN 128
#define BK 32
#define NK (Kk / BK)          // 16 stages

#define A_PITCH 40            // bf16 elems per A smem row (32 + 8 pad) -> 80 B
#define B_PITCH 136           // bf16 elems per B smem row (128 + 8 pad) -> 272 B
#define A_BYTES (BM * A_PITCH * 2)   // 10240
#define B_BYTES (BK * B_PITCH * 2)   // 8704
#define ST_AH 0
#define ST_AL A_BYTES
#define ST_BH (2 * A_BYTES)
#define ST_BL (2 * A_BYTES + B_BYTES)
#define STAGE_BYTES (2 * A_BYTES + 2 * B_BYTES)   // 37888
#define GEMM_SMEM (2 * STAGE_BYTES)               // 75776

__device__ __forceinline__ uint32_t smem_u32(const void* p) {
    uint32_t a;
    asm("{ .reg .u64 t; cvta.to.shared.u64 t, %1; cvt.u32.u64 %0, t; }"
        : "=r"(a) : "l"(p));
    return a;
}
__device__ __forceinline__ void cp16(uint32_t dst, const void* src) {
    asm volatile("cp.async.cg.shared.global [%0], [%1], 16;"
                 :: "r"(dst), "l"(src) : "memory");
}
__device__ __forceinline__ void ldsm_x4(uint32_t* r, uint32_t addr) {
    asm volatile("ldmatrix.sync.aligned.m8n8.x4.shared.b16 {%0,%1,%2,%3}, [%4];"
                 : "=r"(r[0]), "=r"(r[1]), "=r"(r[2]), "=r"(r[3]) : "r"(addr));
}
__device__ __forceinline__ void ldsm_x4t(uint32_t* r, uint32_t addr) {
    asm volatile("ldmatrix.sync.aligned.m8n8.x4.trans.shared.b16 {%0,%1,%2,%3}, [%4];"
                 : "=r"(r[0]), "=r"(r[1]), "=r"(r[2]), "=r"(r[3]) : "r"(addr));
}
__device__ __forceinline__ void mma16816(float* d, const uint32_t* a, const uint32_t* b) {
    asm volatile(
        "mma.sync.aligned.m16n8k16.row.col.f32.bf16.bf16.f32 "
        "{%0,%1,%2,%3}, {%4,%5,%6,%7}, {%8,%9}, {%0,%1,%2,%3};"
        : "+f"(d[0]), "+f"(d[1]), "+f"(d[2]), "+f"(d[3])
        : "r"(a[0]), "r"(a[1]), "r"(a[2]), "r"(a[3]), "r"(b[0]), "r"(b[1]));
}

__global__ __launch_bounds__(256, 2) void gemm_mma_kernel(const float* __restrict__ bias) {
    extern __shared__ char smem[];
    const uint32_t sbase = smem_u32(smem);
    const int tid = threadIdx.x;
    const int wid = tid >> 5;
    const int ln = tid & 31;
    const int warp_m = wid & 3;       // 4 warps along M (32 rows each)
    const int warp_n = wid >> 2;      // 2 warps along N (64 cols each)
    const int bm = blockIdx.y * BM;
    const int bn = blockIdx.x * BN;

    // --- cp.async tile loader ---
    // A: 512 16B-chunks per array: chunk c -> row c>>2, seg c&3
    const int a_row0 = tid >> 2, a_seg = tid & 3;
    const int a_row1 = a_row0 + 64;
    // B: 512 chunks per array: chunk c -> row c>>4, seg c&15
    const int b_row0 = tid >> 4, b_seg = tid & 15;
    const int b_row1 = b_row0 + 16;

    auto load_stage = [&](int it, int p) {
        const int k0 = it * BK;
        const uint32_t st = sbase + p * STAGE_BYTES;
        // A hi/lo
        {
            const size_t g0 = (size_t)(bm + a_row0) * Kk + k0 + a_seg * 8;
            const size_t g1 = (size_t)(bm + a_row1) * Kk + k0 + a_seg * 8;
            const uint32_t s0 = st + ST_AH + a_row0 * (A_PITCH * 2) + a_seg * 16;
            const uint32_t s1 = st + ST_AH + a_row1 * (A_PITCH * 2) + a_seg * 16;
            cp16(s0, g_Ehi + g0);
            cp16(s1, g_Ehi + g1);
            cp16(s0 + (ST_AL - ST_AH), g_Elo + g0);
            cp16(s1 + (ST_AL - ST_AH), g_Elo + g1);
        }
        // B hi/lo
        {
            const size_t g0 = (size_t)(k0 + b_row0) * Nc + bn + b_seg * 8;
            const size_t g1 = (size_t)(k0 + b_row1) * Nc + bn + b_seg * 8;
            const uint32_t s0 = st + ST_BH + b_row0 * (B_PITCH * 2) + b_seg * 16;
            const uint32_t s1 = st + ST_BH + b_row1 * (B_PITCH * 2) + b_seg * 16;
            cp16(s0, g_Whi + g0);
            cp16(s1, g_Whi + g1);
            cp16(s0 + (ST_BL - ST_BH), g_Wlo + g0);
            cp16(s1 + (ST_BL - ST_BH), g_Wlo + g1);
        }
        asm volatile("cp.async.commit_group;" ::: "memory");
    };

    float acc[2][8][4];
#pragma unroll
    for (int i = 0; i < 2; i++)
#pragma unroll
        for (int n = 0; n < 8; n++)
#pragma unroll
            for (int c = 0; c < 4; c++) acc[i][n][c] = 0.0f;

    // ldmatrix per-thread address components
    const int lm_row = ln & 15;             // 0..15
    const int lm_half = ln >> 4;            // 0..1

    load_stage(0, 0);

    for (int it = 0; it < NK; it++) {
        const int p = it & 1;
        if (it + 1 < NK) load_stage(it + 1, p ^ 1);
        if (it + 1 < NK) { asm volatile("cp.async.wait_group 1;" ::: "memory"); }
        else             { asm volatile("cp.async.wait_group 0;" ::: "memory"); }
        __syncthreads();

        const uint32_t st = sbase + p * STAGE_BYTES;
        const uint32_t a_hi = st + ST_AH, a_lo = st + ST_AL;
        const uint32_t b_hi = st + ST_BH, b_lo = st + ST_BL;

#pragma unroll
        for (int j = 0; j < 2; j++) {       // k16 sub-steps within BK=32
            uint32_t ah[2][4], al[2][4], bh[8][2], bl[8][2];
            // A frags: rows warp_m*32 + i*16 + lm_row, k = j*16 + lm_half*8
#pragma unroll
            for (int i = 0; i < 2; i++) {
                const uint32_t off =
                    (uint32_t)(warp_m * 32 + i * 16 + lm_row) * (A_PITCH * 2)
                    + (uint32_t)(j * 16 + lm_half * 8) * 2;
                ldsm_x4(ah[i], a_hi + off);
                ldsm_x4(al[i], a_lo + off);
            }
            // B frags: rows k = j*16 + lm_row, cols warp_n*64 + p4*16 + lm_half*8
#pragma unroll
            for (int p4 = 0; p4 < 4; p4++) {
                const uint32_t off =
                    (uint32_t)(j * 16 + lm_row) * (B_PITCH * 2)
                    + (uint32_t)(warp_n * 64 + p4 * 16 + lm_half * 8) * 2;
                uint32_t r[4];
                ldsm_x4t(r, b_hi + off);
                bh[2 * p4][0] = r[0]; bh[2 * p4][1] = r[1];
                bh[2 * p4 + 1][0] = r[2]; bh[2 * p4 + 1][1] = r[3];
                ldsm_x4t(r, b_lo + off);
                bl[2 * p4][0] = r[0]; bl[2 * p4][1] = r[1];
                bl[2 * p4 + 1][0] = r[2]; bl[2 * p4 + 1][1] = r[3];
            }
            // 3-term split MMA
#pragma unroll
            for (int i = 0; i < 2; i++)
#pragma unroll
                for (int n = 0; n < 8; n++) {
                    mma16816(acc[i][n], ah[i], bh[n]);
                    mma16816(acc[i][n], ah[i], bl[n]);
                    mma16816(acc[i][n], al[i], bh[n]);
                }
        }
        __syncthreads();
    }

    // Epilogue: bias + sigmoid -> g_pop_rates
    const int er = ln >> 2;        // 0..7
    const int ec = (ln & 3) * 2;   // 0,2,4,6
#pragma unroll
    for (int i = 0; i < 2; i++) {
        const int row0 = bm + warp_m * 32 + i * 16 + er;
#pragma unroll
        for (int n = 0; n < 8; n++) {
            const int col = bn + warp_n * 64 + n * 8 + ec;
            const float b0 = __ldg(bias + col);
            const float b1 = __ldg(bias + col + 1);
            float2 v0, v1;
            v0.x = 1.0f / (1.0f + expf(-(acc[i][n][0] + b0)));
            v0.y = 1.0f / (1.0f + expf(-(acc[i][n][1] + b1)));
            v1.x = 1.0f / (1.0f + expf(-(acc[i][n][2] + b0)));
            v1.y = 1.0f / (1.0f + expf(-(acc[i][n][3] + b1)));
            *(float2*)(g_pop_rates + (size_t)row0 * Nc + col) = v0;
            *(float2*)(g_pop_rates + (size_t)(row0 + 8) * Nc + col) = v1;
        }
    }
}

// ---------------------------------------------------------------------------
// Accurate fp32 sin (Cody-Waite + degree-9 minimax); fast-math immune.
// ---------------------------------------------------------------------------
__device__ __forceinline__ float my_sinf(float x) {
    const float INV_PI = 0.318309886183790672f;
    const float PI_HI = 3.14159274101257324f;
    const float PI_LO = -8.74227765734758577e-08f;
    float kf = rintf(x * INV_PI);
    float r = fmaf(-kf, PI_HI, x);
    r = fmaf(-kf, PI_LO, r);
    float s = r * r;
    float p = fmaf(s, 2.6083159809786593e-06f, -1.9810690719168633e-04f);
    p = fmaf(s, p, 8.3330785855650902e-03f);
    p = fmaf(s, p, -1.6666659712791443e-01f);
    float res = fmaf(r * s, p, r);
    int k = (int)kf;
    return (k & 1) ? -res : res;
}

// ---------------------------------------------------------------------------
// Fused encoder: one thread per (b,s,d), loop over T=16. Streaming loads.
// ---------------------------------------------------------------------------
__global__ __launch_bounds__(256) void encode_kernel(
    const float* __restrict__ emb,
    const float* __restrict__ noise,
    const float* __restrict__ freq_bands,
    const float* __restrict__ enc_w,
    const float* __restrict__ rate_rand,
    const float* __restrict__ pop_rand,
    float* __restrict__ out)
{
    const int idx = blockIdx.x * 256 + threadIdx.x;
    const int d = idx & (Dd - 1);
    const int s = (idx >> 9) & (Ss - 1);
    const int b = idx >> 17;

    float w0 = enc_w[0], w1 = enc_w[1], w2 = enc_w[2], w3 = enc_w[3];
    {
        float mx = fmaxf(fmaxf(w0, w1), fmaxf(w2, w3));
        float e0 = expf(w0 - mx), e1 = expf(w1 - mx);
        float e2 = expf(w2 - mx), e3 = expf(w3 - mx);
        float inv = 1.0f / (e0 + e1 + e2 + e3);
        w0 = e0 * inv; w1 = e1 * inv; w2 = e2 * inv; w3 = e3 * inv;
    }

    const float e = emb[idx];
    const float nz = noise[idx];
    const float sig = 1.0f / (1.0f + expf(-e));
    float rate = sig * 0.9f + 0.05f + nz * 0.1f;
    rate = fminf(fmaxf(rate, 0.0f), 1.0f);
    const int st = (int)(sig * 15.0f);
    const float phase = sig * 6.28318530717958647692f;
    const float freq = freq_bands[d];

    const float4* prp = (const float4*)(g_pop_rates + (size_t)idx * Nn);
    const float4 pr0 = prp[0];
    const float4 pr1 = prp[1];

    const float tstep = 6.28318530717958647692f / 15.0f;
    const size_t base = (((size_t)b * Tt) * Ss + s) * Dd + d;
#pragma unroll 4
    for (int t = 0; t < Tt; t++) {
        const size_t o = base + (size_t)t * (Ss * Dd);
        const float rr = __ldcs(rate_rand + o);
        const float4* pp = (const float4*)(pop_rand + o * Nn);
        const float4 q0 = __ldcs(pp);
        const float4 q1 = __ldcs(pp + 1);
        int cnt = (q0.x < pr0.x) + (q0.y < pr0.y) + (q0.z < pr0.z) + (q0.w < pr0.w)
                + (q1.x < pr1.x) + (q1.y < pr1.y) + (q1.z < pr1.z) + (q1.w < pr1.w);

        const float wave = my_sinf(fmaf(freq, (float)t * tstep, phase));

        float val = w0 * ((rr < rate) ? 1.0f : 0.0f)
                  + w1 * ((t == st) ? 1.0f : 0.0f)
                  + w2 * ((float)cnt * 0.125f)
                  + w3 * ((wave > 0.5f) ? 1.0f : 0.0f);
        out[o] = val;
    }
}

// ---------------------------------------------------------------------------
// Launch
// ---------------------------------------------------------------------------
extern "C" void kernel_launch(void* const* d_in, const int* in_sizes, int n_in,
                              void* d_out, int out_size) {
    const float* emb       = (const float*)d_in[0];
    const float* popW      = (const float*)d_in[1];
    const float* popb      = (const float*)d_in[2];
    const float* freq      = (const float*)d_in[3];
    const float* encw      = (const float*)d_in[4];
    const float* noise     = (const float*)d_in[5];
    const float* rate_rand = (const float*)d_in[6];
    const float* pop_rand  = (const float*)d_in[7];
    float* out = (float*)d_out;

    cudaFuncSetAttribute(gemm_mma_kernel,
                         cudaFuncAttributeMaxDynamicSharedMemorySize, GEMM_SMEM);

    conv_kernel<<<(E_F4 + W_F4) / 256, 256>>>(emb, popW);
    gemm_mma_kernel<<<dim3(Nc / BN, Mm / BM), 256, GEMM_SMEM>>>(popb);
    encode_kernel<<<(Mm * Dd) / 256, 256>>>(emb, noise, freq, encw,
                                            rate_rand, pop_rand, out);
}